// round 6
// baseline (speedup 1.0000x reference)
#include <cuda_runtime.h>

#define NCAM 6
#define C    64
#define HF   64
#define WF   176
#define NY   4
#define ZD   129
#define XD   129
#define NH   3
#define DD   128
#define WDIM 128
#define NVOX (NH * DD * WDIM)   // 49152

// 128-byte per-(voxel,cam) descriptor
struct Desc {
    int4   off[4];    // 16 texel offsets (float2 units), row-major [y][x]
    float4 cxv;       // { (1-wxl), wxl, -(1-wxr), -wxr }
    float4 cyv;       // { (1-wyt), wyt, -(1-wyb), -wyb }
    float4 area_pad;  // .x = area
};

// Scratch (static device globals: allocation-free per harness rules)
__device__ float  g_tmpi[NCAM * C * HF * WF];    // [n][c][h][w]
__device__ float  g_integ[NCAM * HF * WF * C];   // [n][h][w][c]
__device__ float2 g_nc[NCAM * NY * ZD * XD];     // projected corners
__device__ Desc   g_desc[NVOX * NCAM];           // 37.7 MB
__device__ unsigned long long g_mask[NVOX];      // byte n = cam n active

// ---------------------------------------------------------------------------
// Kernel 1: integral image per (n,c), coalesced channel-major write
// ---------------------------------------------------------------------------
__global__ void __launch_bounds__(256) integral_kernel(const float* __restrict__ feat) {
    __shared__ float tile[HF * WF];
    const int ncid = blockIdx.x;
    const int tid = threadIdx.x;

    const float* src = feat + (size_t)ncid * HF * WF;
    for (int i = tid; i < HF * WF; i += 256) tile[i] = src[i];
    __syncthreads();

    const int lane = tid & 31, wp = tid >> 5;
    for (int row = wp; row < HF; row += 8) {
        float carry = 0.f;
        #pragma unroll
        for (int seg = 0; seg < 6; seg++) {
            int w = seg * 32 + lane;
            float v = (w < WF) ? tile[row * WF + w] : 0.f;
            #pragma unroll
            for (int off = 1; off < 32; off <<= 1) {
                float u = __shfl_up_sync(0xffffffffu, v, off);
                if (lane >= off) v += u;
            }
            v += carry;
            if (w < WF) tile[row * WF + w] = v;
            carry = __shfl_sync(0xffffffffu, v, 31);
        }
    }
    __syncthreads();

    if (tid < WF) {
        float acc = 0.f;
        #pragma unroll 4
        for (int h = 0; h < HF; h++) {
            acc += tile[h * WF + tid];
            tile[h * WF + tid] = acc;
        }
    }
    __syncthreads();

    float* dst = g_tmpi + (size_t)ncid * HF * WF;
    for (int i = tid; i < HF * WF; i += 256) dst[i] = tile[i];
}

// ---------------------------------------------------------------------------
// Kernel 1b: transpose [n][c][h][w] -> [n][h][w][c]
// ---------------------------------------------------------------------------
__global__ void __launch_bounds__(256) transpose_kernel() {
    __shared__ float tile[C * 33];
    const int n  = blockIdx.z;
    const int h  = blockIdx.y;
    const int w0 = blockIdx.x * 32;

    const float* src = g_tmpi + ((size_t)n * C * HF + h) * WF;
    for (int idx = threadIdx.x; idx < C * 32; idx += 256) {
        int c = idx >> 5, w = idx & 31;
        int gw = w0 + w;
        tile[c * 33 + w] = (gw < WF) ? src[(size_t)c * HF * WF + gw] : 0.f;
    }
    __syncthreads();

    float* dst = g_integ + (((size_t)n * HF + h) * WF) * C;
    for (int idx = threadIdx.x; idx < C * 32; idx += 256) {
        int w = idx >> 6, c = idx & 63;
        int gw = w0 + w;
        if (gw < WF) dst[(size_t)gw * C + c] = tile[c * 33 + w];
    }
}

// ---------------------------------------------------------------------------
// Kernel 2: project grid corners
// ---------------------------------------------------------------------------
__global__ void proj_kernel(const float* __restrict__ ks,
                            const float* __restrict__ m2c,
                            const float* __restrict__ prot,
                            const float* __restrict__ ptran,
                            const float* __restrict__ und,
                            const float* __restrict__ grid) {
    const int id = blockIdx.x * blockDim.x + threadIdx.x;
    const int total = NCAM * NY * ZD * XD;
    if (id >= total) return;
    const int xi = id % XD;
    const int zi = (id / XD) % ZD;
    const int ny = (id / (XD * ZD)) % NY;
    const int n  = id / (XD * ZD * NY);

    const float* K  = ks    + n * 9;
    const float* M  = m2c   + n * 12;
    const float* PR = prot  + n * 9;
    const float* PT = ptran + n * 3;
    const float* Dd = und   + n * 7;

    float cal[3][4];
    #pragma unroll
    for (int i = 0; i < 3; i++)
        #pragma unroll
        for (int j = 0; j < 4; j++)
            cal[i][j] = K[i*3+0]*M[0*4+j] + K[i*3+1]*M[1*4+j] + K[i*3+2]*M[2*4+j];

    const float* g = grid + ((size_t)zi * XD + xi) * 3;
    const float vx = g[0];
    const float vy = g[1] + (2.0f - (float)ny);
    const float vz = g[2];

    float hx = cal[0][0]*vx + cal[0][1]*vy + cal[0][2]*vz + cal[0][3];
    float hy = cal[1][0]*vx + cal[1][1]*vy + cal[1][2]*vz + cal[1][3];
    float hz = cal[2][0]*vx + cal[2][1]*vy + cal[2][2]*vz + cal[2][3];

    const float posf = (hz > 0.f) ? 1.f : 0.f;
    hx *= posf; hy *= posf;
    const float px = hx / hz, py = hy / hz;

    const float cx = K[2], cy = K[5], fx = K[0], fy = K[4];
    const float x = (px - cx) / fx, y = (py - cy) / fy;

    float xd, yd;
    if (Dd[6] == 1.0f) {
        float r  = sqrtf(x*x + y*y);
        float th = atanf(r);
        float t2 = th * th;
        float t4 = t2 * t2;
        float rad = th * (1.f + Dd[0]*t2 + Dd[1]*t4 + Dd[2]*t4*t2 + Dd[5]*t4*t4) / r;
        xd = x * rad * fx + cx;
        yd = y * rad * fy + cy;
    } else {
        float r2 = x*x + y*y;
        float r4 = r2 * r2;
        float poly = 1.f + Dd[0]*r2 + Dd[1]*r4 + Dd[2]*r4*r2;
        float p1 = Dd[3], p2 = Dd[4];
        float xdd = x*poly + (2.f*p1*x*y + p2*(r2 + 2.f*x*x));
        float ydd = y*poly + (p1*(r2 + 2.f*y*y) + 2.f*p2*x*y);
        xd = xdd * fx + cx;
        yd = ydd * fy + cy;
    }
    xd *= posf; yd *= posf;

    const float qx = PR[0]*xd + PR[1]*yd + PT[0];
    const float qy = PR[3]*xd + PR[4]*yd + PT[1];

    float2 o;
    o.x = fminf(fmaxf(2.f*qx - 1.f, -1.f), 1.f);
    o.y = fminf(fmaxf(2.f*qy - 1.f, -1.f), 1.f);
    g_nc[id] = o;
}

// ---------------------------------------------------------------------------
// Kernel 2b: per (voxel,cam) geometry -> descriptor + active mask
// id = n*NVOX + v  (consecutive threads walk wd: coalesced corner loads)
// ---------------------------------------------------------------------------
__global__ void __launch_bounds__(256) geom_kernel() {
    const int id = blockIdx.x * blockDim.x + threadIdx.x;
    if (id >= NCAM * NVOX) return;
    const int n  = id / NVOX;
    const int v  = id - n * NVOX;
    const int wd = v & (WDIM - 1);
    const int d  = (v >> 7) & (DD - 1);
    const int nh = v >> 14;

    const float2* ncp = g_nc + n * (NY * ZD * XD) + ((size_t)nh * ZD + d) * XD + wd;

    float l = 1e30f, r = -1e30f, tp = 1e30f, bt = -1e30f;
    #pragma unroll
    for (int a = 0; a < 2; a++)
        #pragma unroll
        for (int b = 0; b < 2; b++)
            #pragma unroll
            for (int cc = 0; cc < 2; cc++) {
                float2 p = __ldg(ncp + (a * ZD + b) * XD + cc);
                l  = fminf(l,  p.x); r  = fmaxf(r,  p.x);
                tp = fminf(tp, p.y); bt = fmaxf(bt, p.y);
            }

    const float area = (r - l) * (bt - tp) * (HF * WF * 0.25f) + 1e-6f;
    const unsigned char ok = (area > 1e-6f) ? 1 : 0;
    ((unsigned char*)&g_mask[v])[n] = ok;
    if (!ok) return;                       // stale desc never read (mask deterministic)

    float pxl = fminf(fmaxf((l  + 1.f) * 87.5f, 0.f), 175.f);
    float pxr = fminf(fmaxf((r  + 1.f) * 87.5f, 0.f), 175.f);
    float pyt = fminf(fmaxf((tp + 1.f) * 31.5f, 0.f), 63.f);
    float pyb = fminf(fmaxf((bt + 1.f) * 31.5f, 0.f), 63.f);

    float fxl = floorf(pxl), fxr = floorf(pxr);
    float fyt = floorf(pyt), fyb = floorf(pyb);
    float wxl = pxl - fxl, wxr = pxr - fxr;
    float wyt = pyt - fyt, wyb = pyb - fyb;

    int xs[4], ys[4];
    xs[0] = (int)fxl; xs[1] = min(xs[0] + 1, WF - 1);
    xs[2] = (int)fxr; xs[3] = min(xs[2] + 1, WF - 1);
    ys[0] = (int)fyt; ys[1] = min(ys[0] + 1, HF - 1);
    ys[2] = (int)fyb; ys[3] = min(ys[2] + 1, HF - 1);

    Desc dsc;
    // rows: y order {y0t, y1t, y0b, y1b}; cols: x order {x0l, x1l, x0r, x1r}
    #pragma unroll
    for (int i = 0; i < 4; i++) {
        int yb = ys[i] * WF;
        dsc.off[i] = make_int4((yb + xs[0]) * (C / 2), (yb + xs[1]) * (C / 2),
                               (yb + xs[2]) * (C / 2), (yb + xs[3]) * (C / 2));
    }
    dsc.cxv = make_float4(1.f - wxl, wxl, -(1.f - wxr), -wxr);
    dsc.cyv = make_float4(1.f - wyt, wyt, -(1.f - wyb), -wyb);
    dsc.area_pad = make_float4(area, 0.f, 0.f, 0.f);

    g_desc[(size_t)v * NCAM + n] = dsc;
}

// ---------------------------------------------------------------------------
// Kernel 3: gather + bilinear via precomputed descriptors, max over cams.
// Block 32x8: threadIdx.x = channel pair, threadIdx.y = voxel in 8-run.
// ---------------------------------------------------------------------------
__global__ void __launch_bounds__(256) vox_kernel(float* __restrict__ out) {
    const int nhd = blockIdx.x >> 4;
    const int d   = nhd & 127;
    const int nh  = nhd >> 7;
    const int wd0 = (blockIdx.x & 15) << 3;
    const int wd  = wd0 + threadIdx.y;
    const int t   = threadIdx.x;
    const int v   = (nh * DD + d) * WDIM + wd;

    const unsigned long long mask = __ldg(&g_mask[v]);

    float m0 = -3.402823466e38f, m1 = -3.402823466e38f;

    #pragma unroll 1
    for (int n = 0; n < NCAM; n++) {
        if (!((mask >> (8 * n)) & 1ull)) {
            m0 = fmaxf(m0, 0.f);
            m1 = fmaxf(m1, 0.f);
            continue;
        }
        const Desc* dp = &g_desc[(size_t)v * NCAM + n];
        const int4   o0 = __ldg(&dp->off[0]);
        const int4   o1 = __ldg(&dp->off[1]);
        const int4   o2 = __ldg(&dp->off[2]);
        const int4   o3 = __ldg(&dp->off[3]);
        const float4 cxv = __ldg(&dp->cxv);
        const float4 cyv = __ldg(&dp->cyv);
        const float  area = __ldg(&dp->area_pad.x);

        const float2* base = (const float2*)(g_integ + (size_t)n * HF * WF * C) + t;

        float nx = 0.f, nyv = 0.f;
        {
            float2 a = __ldg(base + o0.x), b = __ldg(base + o0.y);
            float2 c = __ldg(base + o0.z), e = __ldg(base + o0.w);
            float rx = a.x*cxv.x + b.x*cxv.y + c.x*cxv.z + e.x*cxv.w;
            float ry = a.y*cxv.x + b.y*cxv.y + c.y*cxv.z + e.y*cxv.w;
            nx += rx * cyv.x; nyv += ry * cyv.x;
        }
        {
            float2 a = __ldg(base + o1.x), b = __ldg(base + o1.y);
            float2 c = __ldg(base + o1.z), e = __ldg(base + o1.w);
            float rx = a.x*cxv.x + b.x*cxv.y + c.x*cxv.z + e.x*cxv.w;
            float ry = a.y*cxv.x + b.y*cxv.y + c.y*cxv.z + e.y*cxv.w;
            nx += rx * cyv.y; nyv += ry * cyv.y;
        }
        {
            float2 a = __ldg(base + o2.x), b = __ldg(base + o2.y);
            float2 c = __ldg(base + o2.z), e = __ldg(base + o2.w);
            float rx = a.x*cxv.x + b.x*cxv.y + c.x*cxv.z + e.x*cxv.w;
            float ry = a.y*cxv.x + b.y*cxv.y + c.y*cxv.z + e.y*cxv.w;
            nx += rx * cyv.z; nyv += ry * cyv.z;
        }
        {
            float2 a = __ldg(base + o3.x), b = __ldg(base + o3.y);
            float2 c = __ldg(base + o3.z), e = __ldg(base + o3.w);
            float rx = a.x*cxv.x + b.x*cxv.y + c.x*cxv.z + e.x*cxv.w;
            float ry = a.y*cxv.x + b.y*cxv.y + c.y*cxv.z + e.y*cxv.w;
            nx += rx * cyv.w; nyv += ry * cyv.w;
        }
        m0 = fmaxf(m0, nx / area);
        m1 = fmaxf(m1, nyv / area);
    }

    // Stage results in smem, write coalesced 32B segments
    __shared__ float res[C * 9];
    res[(2 * t    ) * 9 + threadIdx.y] = m0;
    res[(2 * t + 1) * 9 + threadIdx.y] = m1;
    __syncthreads();

    const int i = threadIdx.y * 32 + threadIdx.x;
    #pragma unroll
    for (int rep = 0; rep < 2; rep++) {
        int idx = i + rep * 256;
        int ch  = idx >> 3;
        int j   = idx & 7;
        out[((size_t)(ch * NH + nh) * DD + d) * WDIM + wd0 + j] = res[ch * 9 + j];
    }
}

// ---------------------------------------------------------------------------
extern "C" void kernel_launch(void* const* d_in, const int* in_sizes, int n_in,
                              void* d_out, int out_size) {
    (void)in_sizes; (void)n_in; (void)out_size;
    const float* features  = (const float*)d_in[0];
    const float* ks        = (const float*)d_in[1];
    const float* imu2cs    = (const float*)d_in[2];
    const float* post_rots = (const float*)d_in[3];
    const float* post_trans= (const float*)d_in[4];
    const float* undists   = (const float*)d_in[5];
    const float* grid      = (const float*)d_in[6];
    float* out = (float*)d_out;

    integral_kernel<<<NCAM * C, 256>>>(features);

    dim3 tgrid((WF + 31) / 32, HF, NCAM);
    transpose_kernel<<<tgrid, 256>>>();

    const int totalP = NCAM * NY * ZD * XD;
    proj_kernel<<<(totalP + 255) / 256, 256>>>(ks, imu2cs, post_rots, post_trans,
                                               undists, grid);

    geom_kernel<<<(NCAM * NVOX + 255) / 256, 256>>>();

    dim3 blk(32, 8);
    vox_kernel<<<(NH * DD * WDIM) / 8, blk>>>(out);
}

// round 7
// speedup vs baseline: 1.1554x; 1.1554x over previous
#include <cuda_runtime.h>

#define NCAM 6
#define C    64
#define HF   64
#define WF   176
#define NY   4
#define ZD   129
#define XD   129
#define NH   3
#define DD   128
#define WDIM 128
#define NVOX (NH * DD * WDIM)   // 49152

// Scratch (static device globals: allocation-free per harness rules)
__device__ float  g_tmpi[NCAM * C * HF * WF];    // [n][c][h][w]
__device__ float  g_integ[NCAM * HF * WF * C];   // [n][h][w][c]
__device__ float2 g_nc[NCAM * NY * ZD * XD];     // projected corners

// ---------------------------------------------------------------------------
// Kernel 1: integral image per (n,c), coalesced channel-major write
// ---------------------------------------------------------------------------
__global__ void __launch_bounds__(256) integral_kernel(const float* __restrict__ feat) {
    __shared__ float tile[HF * WF];
    const int ncid = blockIdx.x;
    const int tid = threadIdx.x;

    const float* src = feat + (size_t)ncid * HF * WF;
    for (int i = tid; i < HF * WF; i += 256) tile[i] = src[i];
    __syncthreads();

    const int lane = tid & 31, wp = tid >> 5;
    for (int row = wp; row < HF; row += 8) {
        float carry = 0.f;
        #pragma unroll
        for (int seg = 0; seg < 6; seg++) {
            int w = seg * 32 + lane;
            float v = (w < WF) ? tile[row * WF + w] : 0.f;
            #pragma unroll
            for (int off = 1; off < 32; off <<= 1) {
                float u = __shfl_up_sync(0xffffffffu, v, off);
                if (lane >= off) v += u;
            }
            v += carry;
            if (w < WF) tile[row * WF + w] = v;
            carry = __shfl_sync(0xffffffffu, v, 31);
        }
    }
    __syncthreads();

    if (tid < WF) {
        float acc = 0.f;
        #pragma unroll 4
        for (int h = 0; h < HF; h++) {
            acc += tile[h * WF + tid];
            tile[h * WF + tid] = acc;
        }
    }
    __syncthreads();

    float* dst = g_tmpi + (size_t)ncid * HF * WF;
    for (int i = tid; i < HF * WF; i += 256) dst[i] = tile[i];
}

// ---------------------------------------------------------------------------
// Kernel 1b: transpose [n][c][h][w] -> [n][h][w][c]
// ---------------------------------------------------------------------------
__global__ void __launch_bounds__(256) transpose_kernel() {
    __shared__ float tile[C * 33];
    const int n  = blockIdx.z;
    const int h  = blockIdx.y;
    const int w0 = blockIdx.x * 32;

    const float* src = g_tmpi + ((size_t)n * C * HF + h) * WF;
    for (int idx = threadIdx.x; idx < C * 32; idx += 256) {
        int c = idx >> 5, w = idx & 31;
        int gw = w0 + w;
        tile[c * 33 + w] = (gw < WF) ? src[(size_t)c * HF * WF + gw] : 0.f;
    }
    __syncthreads();

    float* dst = g_integ + (((size_t)n * HF + h) * WF) * C;
    for (int idx = threadIdx.x; idx < C * 32; idx += 256) {
        int w = idx >> 6, c = idx & 63;
        int gw = w0 + w;
        if (gw < WF) dst[(size_t)gw * C + c] = tile[c * 33 + w];
    }
}

// ---------------------------------------------------------------------------
// Kernel 2: project grid corners
// ---------------------------------------------------------------------------
__global__ void proj_kernel(const float* __restrict__ ks,
                            const float* __restrict__ m2c,
                            const float* __restrict__ prot,
                            const float* __restrict__ ptran,
                            const float* __restrict__ und,
                            const float* __restrict__ grid) {
    const int id = blockIdx.x * blockDim.x + threadIdx.x;
    const int total = NCAM * NY * ZD * XD;
    if (id >= total) return;
    const int xi = id % XD;
    const int zi = (id / XD) % ZD;
    const int ny = (id / (XD * ZD)) % NY;
    const int n  = id / (XD * ZD * NY);

    const float* K  = ks    + n * 9;
    const float* M  = m2c   + n * 12;
    const float* PR = prot  + n * 9;
    const float* PT = ptran + n * 3;
    const float* Dd = und   + n * 7;

    float cal[3][4];
    #pragma unroll
    for (int i = 0; i < 3; i++)
        #pragma unroll
        for (int j = 0; j < 4; j++)
            cal[i][j] = K[i*3+0]*M[0*4+j] + K[i*3+1]*M[1*4+j] + K[i*3+2]*M[2*4+j];

    const float* g = grid + ((size_t)zi * XD + xi) * 3;
    const float vx = g[0];
    const float vy = g[1] + (2.0f - (float)ny);
    const float vz = g[2];

    float hx = cal[0][0]*vx + cal[0][1]*vy + cal[0][2]*vz + cal[0][3];
    float hy = cal[1][0]*vx + cal[1][1]*vy + cal[1][2]*vz + cal[1][3];
    float hz = cal[2][0]*vx + cal[2][1]*vy + cal[2][2]*vz + cal[2][3];

    const float posf = (hz > 0.f) ? 1.f : 0.f;
    hx *= posf; hy *= posf;
    const float px = hx / hz, py = hy / hz;

    const float cx = K[2], cy = K[5], fx = K[0], fy = K[4];
    const float x = (px - cx) / fx, y = (py - cy) / fy;

    float xd, yd;
    if (Dd[6] == 1.0f) {
        float r  = sqrtf(x*x + y*y);
        float th = atanf(r);
        float t2 = th * th;
        float t4 = t2 * t2;
        float rad = th * (1.f + Dd[0]*t2 + Dd[1]*t4 + Dd[2]*t4*t2 + Dd[5]*t4*t4) / r;
        xd = x * rad * fx + cx;
        yd = y * rad * fy + cy;
    } else {
        float r2 = x*x + y*y;
        float r4 = r2 * r2;
        float poly = 1.f + Dd[0]*r2 + Dd[1]*r4 + Dd[2]*r4*r2;
        float p1 = Dd[3], p2 = Dd[4];
        float xdd = x*poly + (2.f*p1*x*y + p2*(r2 + 2.f*x*x));
        float ydd = y*poly + (p1*(r2 + 2.f*y*y) + 2.f*p2*x*y);
        xd = xdd * fx + cx;
        yd = ydd * fy + cy;
    }
    xd *= posf; yd *= posf;

    const float qx = PR[0]*xd + PR[1]*yd + PT[0];
    const float qy = PR[3]*xd + PR[4]*yd + PT[1];

    float2 o;
    o.x = fminf(fmaxf(2.f*qx - 1.f, -1.f), 1.f);
    o.y = fminf(fmaxf(2.f*qy - 1.f, -1.f), 1.f);
    g_nc[id] = o;
}

// ---------------------------------------------------------------------------
// Kernel 3: fused geometry (smem descriptors, 48 tasks per block) + gather.
// Block 32x8: threadIdx.x = channel pair, threadIdx.y = voxel in 8-run.
// Descriptor: 16 texel offsets + 16 combined coefficients c_ij = cy_i*cx_j/area
// (signs and 1/area folded in) + active flag. All broadcast-read from smem.
// ---------------------------------------------------------------------------
__global__ void __launch_bounds__(256) vox_kernel(float* __restrict__ out) {
    const int nhd = blockIdx.x >> 4;
    const int d   = nhd & 127;
    const int nh  = nhd >> 7;
    const int wd0 = (blockIdx.x & 15) << 3;
    const int tid = threadIdx.y * 32 + threadIdx.x;

    __shared__ int   s_off[48 * 16];    // texel offsets (float2 units)
    __shared__ float s_c[48 * 16];      // combined coefficients
    __shared__ int   s_act[48];         // active flag per (cam,voxel)
    __shared__ float res[C * 9];        // output staging

    // ---- Geometry phase: one task per thread, task = cam*8 + vy ----
    if (tid < 48) {
        const int cam = tid >> 3, vy = tid & 7;
        const int wd = wd0 + vy;
        const float2* ncp = g_nc + cam * (NY * ZD * XD) + ((size_t)nh * ZD + d) * XD + wd;

        float l = 1e30f, r = -1e30f, tp = 1e30f, bt = -1e30f;
        #pragma unroll
        for (int a = 0; a < 2; a++)
            #pragma unroll
            for (int b = 0; b < 2; b++)
                #pragma unroll
                for (int cc2 = 0; cc2 < 2; cc2++) {
                    float2 p = __ldg(ncp + (a * ZD + b) * XD + cc2);
                    l  = fminf(l,  p.x); r  = fmaxf(r,  p.x);
                    tp = fminf(tp, p.y); bt = fmaxf(bt, p.y);
                }

        const float area = (r - l) * (bt - tp) * (HF * WF * 0.25f) + 1e-6f;
        const int ok = (area > 1e-6f) ? 1 : 0;
        s_act[tid] = ok;
        if (ok) {
            float pxl = fminf(fmaxf((l  + 1.f) * 87.5f, 0.f), 175.f);
            float pxr = fminf(fmaxf((r  + 1.f) * 87.5f, 0.f), 175.f);
            float pyt = fminf(fmaxf((tp + 1.f) * 31.5f, 0.f), 63.f);
            float pyb = fminf(fmaxf((bt + 1.f) * 31.5f, 0.f), 63.f);

            float fxl = floorf(pxl), fxr = floorf(pxr);
            float fyt = floorf(pyt), fyb = floorf(pyb);
            float wxl = pxl - fxl, wxr = pxr - fxr;
            float wyt = pyt - fyt, wyb = pyb - fyb;

            int xs[4], ys[4];
            xs[0] = (int)fxl; xs[1] = min(xs[0] + 1, WF - 1);
            xs[2] = (int)fxr; xs[3] = min(xs[2] + 1, WF - 1);
            ys[0] = (int)fyt; ys[1] = min(ys[0] + 1, HF - 1);
            ys[2] = (int)fyb; ys[3] = min(ys[2] + 1, HF - 1);

            const float inv = 1.0f / area;
            // cx: {+(1-wxl), +wxl, -(1-wxr), -wxr}; cy: {+(1-wyt), +wyt, -(1-wyb), -wyb}
            float cxv[4] = {1.f - wxl, wxl, -(1.f - wxr), -wxr};
            float cyv[4] = {(1.f - wyt) * inv, wyt * inv, -(1.f - wyb) * inv, -wyb * inv};

            #pragma unroll
            for (int i = 0; i < 4; i++) {
                const int yb = ys[i] * WF;
                #pragma unroll
                for (int j = 0; j < 4; j++) {
                    s_off[tid * 16 + i * 4 + j] = (yb + xs[j]) * (C / 2);
                    s_c[tid * 16 + i * 4 + j]   = cyv[i] * cxv[j];
                }
            }
        }
    }
    __syncthreads();

    // ---- Gather phase ----
    const int t = threadIdx.x;                   // channel pair
    float m0 = -3.402823466e38f, m1 = -3.402823466e38f;

    #pragma unroll 1
    for (int n = 0; n < NCAM; n++) {
        const int task = n * 8 + threadIdx.y;
        if (!s_act[task]) {
            m0 = fmaxf(m0, 0.f);
            m1 = fmaxf(m1, 0.f);
            continue;
        }
        const int4*   so = (const int4*)  (s_off + task * 16);
        const float4* sc = (const float4*)(s_c   + task * 16);
        const float2* base = (const float2*)(g_integ + (size_t)n * HF * WF * C) + t;

        float nx = 0.f, nyv = 0.f;
        #pragma unroll
        for (int g = 0; g < 4; g++) {
            const int4   o  = so[g];
            const float4 cc = sc[g];
            float2 a = __ldg(base + o.x), b = __ldg(base + o.y);
            float2 c = __ldg(base + o.z), e = __ldg(base + o.w);
            nx  = fmaf(a.x, cc.x, fmaf(b.x, cc.y, fmaf(c.x, cc.z, fmaf(e.x, cc.w, nx))));
            nyv = fmaf(a.y, cc.x, fmaf(b.y, cc.y, fmaf(c.y, cc.z, fmaf(e.y, cc.w, nyv))));
        }
        m0 = fmaxf(m0, nx);
        m1 = fmaxf(m1, nyv);
    }

    // ---- Output staging: coalesced 32B segments ----
    res[(2 * t    ) * 9 + threadIdx.y] = m0;
    res[(2 * t + 1) * 9 + threadIdx.y] = m1;
    __syncthreads();

    #pragma unroll
    for (int rep = 0; rep < 2; rep++) {
        int idx = tid + rep * 256;               // 0..511 = c*8 + j
        int ch  = idx >> 3;
        int j   = idx & 7;
        out[((size_t)(ch * NH + nh) * DD + d) * WDIM + wd0 + j] = res[ch * 9 + j];
    }
}

// ---------------------------------------------------------------------------
extern "C" void kernel_launch(void* const* d_in, const int* in_sizes, int n_in,
                              void* d_out, int out_size) {
    (void)in_sizes; (void)n_in; (void)out_size;
    const float* features  = (const float*)d_in[0];
    const float* ks        = (const float*)d_in[1];
    const float* imu2cs    = (const float*)d_in[2];
    const float* post_rots = (const float*)d_in[3];
    const float* post_trans= (const float*)d_in[4];
    const float* undists   = (const float*)d_in[5];
    const float* grid      = (const float*)d_in[6];
    float* out = (float*)d_out;

    integral_kernel<<<NCAM * C, 256>>>(features);

    dim3 tgrid((WF + 31) / 32, HF, NCAM);
    transpose_kernel<<<tgrid, 256>>>();

    const int totalP = NCAM * NY * ZD * XD;
    proj_kernel<<<(totalP + 255) / 256, 256>>>(ks, imu2cs, post_rots, post_trans,
                                               undists, grid);

    dim3 blk(32, 8);
    vox_kernel<<<(NH * DD * WDIM) / 8, blk>>>(out);
}